// round 5
// baseline (speedup 1.0000x reference)
#include <cuda_runtime.h>

#define NNODES 50000
#define DIM 256
#define NEDGE 400000
#define HEADS 8
#define DHEAD 32
#define CONCATD 1280
#define NCLS 7
#define EPSBN 1e-9f

static inline int cdiv(int a, int b) { return (a + b - 1) / b; }

// ---------------- scratch (device globals; no allocations allowed) ----------
__device__ float g_buf0[NNODES * DIM];
__device__ float g_buf1[NNODES * DIM];
__device__ float g_buf2[NNODES * DIM];
__device__ float g_atts[NNODES * HEADS];
__device__ float g_attn[NNODES * HEADS];
__device__ float g_concat[NNODES * CONCATD];
__device__ float g_stats[2 * DIM];
__device__ float g_wpack[2 * 2 * DIM * DIM];  // [layer][self/neigh][d][h*32+k]

// ---------------- utility ----------------
__global__ void zero_kernel(float* p, size_t n4) {
    size_t i = (blockIdx.x * (size_t)blockDim.x + threadIdx.x);
    if (i < n4) reinterpret_cast<float4*>(p)[i] = make_float4(0.f, 0.f, 0.f, 0.f);
}

// Repack gat W [2,8,256,32] -> [2][2][256][256] flat (d-major, col = h*32+k)
__global__ void repack_kernel(const float* __restrict__ Ws, const float* __restrict__ Wn) {
    int idx = blockIdx.x * blockDim.x + threadIdx.x;
    if (idx >= 2 * HEADS * DIM * DHEAD) return;
    int l = idx / (HEADS * DIM * DHEAD);
    int rem = idx % (HEADS * DIM * DHEAD);
    int h = rem / (DIM * DHEAD);
    int d = (rem / DHEAD) % DIM;
    int k = rem % DHEAD;
    int dst = l * (2 * DIM * DIM) + d * DIM + h * DHEAD + k;
    g_wpack[dst] = Ws[idx];
    g_wpack[dst + DIM * DIM] = Wn[idx];
}

// ---------------- GEMM: C[M,256] = (relu?)(A[M,256] @ B[256,256] + bias) ----
// BM=64, BN=64, BK=16, 256 threads, 4x4 per thread.
template <bool RELU>
__global__ void gemm_kernel(const float* __restrict__ A, const float* __restrict__ B,
                            const float* __restrict__ bias, float* __restrict__ C) {
    __shared__ float As[16][64 + 4];
    __shared__ float Bs[16][64];
    int tid = threadIdx.x;
    int m0 = blockIdx.x * 64;
    int n0 = blockIdx.y * 64;
    int tx = tid & 15, ty = tid >> 4;
    int arow = tid >> 2, ac4 = (tid & 3) * 4;
    int brow = tid >> 4, bc4 = (tid & 15) * 4;
    float acc[4][4] = {};
    for (int k0 = 0; k0 < 256; k0 += 16) {
        float4 av = make_float4(0.f, 0.f, 0.f, 0.f);
        if (m0 + arow < NNODES)
            av = *reinterpret_cast<const float4*>(A + (size_t)(m0 + arow) * 256 + k0 + ac4);
        As[ac4 + 0][arow] = av.x;
        As[ac4 + 1][arow] = av.y;
        As[ac4 + 2][arow] = av.z;
        As[ac4 + 3][arow] = av.w;
        float4 bv = *reinterpret_cast<const float4*>(B + (size_t)(k0 + brow) * 256 + n0 + bc4);
        *reinterpret_cast<float4*>(&Bs[brow][bc4]) = bv;
        __syncthreads();
#pragma unroll
        for (int k = 0; k < 16; ++k) {
            float a[4];
#pragma unroll
            for (int i = 0; i < 4; ++i) a[i] = As[k][ty * 4 + i];
            float4 bq = *reinterpret_cast<float4*>(&Bs[k][tx * 4]);
            float b[4] = {bq.x, bq.y, bq.z, bq.w};
#pragma unroll
            for (int i = 0; i < 4; ++i)
#pragma unroll
                for (int j = 0; j < 4; ++j) acc[i][j] += a[i] * b[j];
        }
        __syncthreads();
    }
#pragma unroll
    for (int i = 0; i < 4; ++i) {
        int m = m0 + ty * 4 + i;
        if (m >= NNODES) break;
#pragma unroll
        for (int j = 0; j < 4; ++j) {
            int n = n0 + tx * 4 + j;
            float v = acc[i][j] + bias[n];
            if (RELU) v = fmaxf(v, 0.f);
            C[(size_t)m * 256 + n] = v;
        }
    }
}

// ---------------- GAT attention logits ----------------
__global__ void att_kernel(const float* __restrict__ fself, const float* __restrict__ a_s,
                           const float* __restrict__ a_n, float* __restrict__ att_s,
                           float* __restrict__ att_n) {
    int i = blockIdx.x * blockDim.x + threadIdx.x;  // i = n*8 + h
    if (i >= NNODES * HEADS) return;
    int h = i & 7;
    const float* f = fself + (size_t)i * 32;  // n*256 + h*32 == i*32
    float ss = 0.f, sn = 0.f;
#pragma unroll
    for (int k = 0; k < 32; ++k) {
        float v = f[k];
        ss += v * a_s[h * 32 + k];
        sn += v * a_n[h * 32 + k];
    }
    att_s[i] = ss < 0.f ? 0.2f * ss : ss;
    att_n[i] = sn < 0.f ? 0.2f * sn : sn;
}

// ---------------- edge aggregation ----------------
// blockDim = (64, 4): 64 lanes per edge, 4 edges per block
__global__ void gat_edge_kernel(const int* __restrict__ row, const int* __restrict__ col,
                                const float* __restrict__ vals, const float* __restrict__ att_s,
                                const float* __restrict__ att_n, const float* __restrict__ fneigh,
                                float* __restrict__ out) {
    int e = blockIdx.x * 4 + threadIdx.y;
    if (e >= NEDGE) return;
    int r = row[e], c = col[e];
    int t = threadIdx.x;  // 0..63
    int h = t >> 3;
    float coef = (att_s[r * 8 + h] + att_n[c * 8 + h]) * vals[e];
    float4 fn = *reinterpret_cast<const float4*>(fneigh + (size_t)c * 256 + t * 4);
    float* o = out + (size_t)r * 256 + t * 4;
    atomicAdd(o + 0, coef * fn.x);
    atomicAdd(o + 1, coef * fn.y);
    atomicAdd(o + 2, coef * fn.z);
    atomicAdd(o + 3, coef * fn.w);
}

__global__ void gcn_edge_kernel(const int* __restrict__ row, const int* __restrict__ col,
                                const float* __restrict__ vals, const float* __restrict__ h,
                                float* __restrict__ out) {
    int e = blockIdx.x * 4 + threadIdx.y;
    if (e >= NEDGE) return;
    int r = row[e], c = col[e];
    float coef = vals[e];
    int t = threadIdx.x;
    float4 fn = *reinterpret_cast<const float4*>(h + (size_t)c * 256 + t * 4);
    float* o = out + (size_t)r * 256 + t * 4;
    atomicAdd(o + 0, coef * fn.x);
    atomicAdd(o + 1, coef * fn.y);
    atomicAdd(o + 2, coef * fn.z);
    atomicAdd(o + 3, coef * fn.w);
}

// ---------------- BatchNorm (training-mode, biased var) ----------------
template <bool RELU>
__global__ void bn_stats_kernel(const float* __restrict__ x, float* __restrict__ stats) {
    int col = threadIdx.x;  // 256 threads
    int r0 = blockIdx.x * 256;
    int rend = min(r0 + 256, NNODES);
    float s = 0.f, s2 = 0.f;
    for (int r = r0; r < rend; ++r) {
        float v = x[(size_t)r * 256 + col];
        if (RELU) v = fmaxf(v, 0.f);
        s += v;
        s2 += v * v;
    }
    atomicAdd(&stats[col], s);
    atomicAdd(&stats[256 + col], s2);
}

template <bool RELU>
__global__ void bn_norm_kernel(const float* __restrict__ x, const float* __restrict__ stats,
                               float* __restrict__ dst, int dstStride) {
    size_t idx = blockIdx.x * (size_t)blockDim.x + threadIdx.x;
    if (idx >= (size_t)NNODES * 256) return;
    int col = (int)(idx & 255);
    size_t rowi = idx >> 8;
    const float invM = 1.f / NNODES;
    float mean = stats[col] * invM;
    float var = stats[256 + col] * invM - mean * mean;
    float istd = rsqrtf(var + EPSBN);
    float v = x[idx];
    if (RELU) v = fmaxf(v, 0.f);
    dst[rowi * dstStride + col] = (v - mean) * istd;
}

// ---------------- classifier: [N,1280] @ [1280,7] + b ----------------
__global__ void cls_kernel(const float* __restrict__ feat, const float* __restrict__ W,
                           const float* __restrict__ b, float* __restrict__ out) {
    __shared__ float sW[CONCATD * NCLS];
    for (int i = threadIdx.x; i < CONCATD * NCLS; i += blockDim.x) sW[i] = W[i];
    __syncthreads();
    int warp = threadIdx.x >> 5, lane = threadIdx.x & 31;
    int n = blockIdx.x * (blockDim.x >> 5) + warp;
    if (n >= NNODES) return;
    float acc[NCLS] = {};
    const float* f = feat + (size_t)n * CONCATD;
    for (int j = lane; j < CONCATD; j += 32) {
        float v = f[j];
#pragma unroll
        for (int c = 0; c < NCLS; ++c) acc[c] += v * sW[j * NCLS + c];
    }
#pragma unroll
    for (int c = 0; c < NCLS; ++c)
        for (int off = 16; off; off >>= 1) acc[c] += __shfl_down_sync(0xffffffffu, acc[c], off);
    if (lane == 0) {
#pragma unroll
        for (int c = 0; c < NCLS; ++c) out[(size_t)n * NCLS + c] = acc[c] + b[c];
    }
}

// ---------------- host orchestration ----------------
extern "C" void kernel_launch(void* const* d_in, const int* in_sizes, int n_in,
                              void* d_out, int out_size) {
    const float* f_in = (const float*)d_in[0];
    const int* erows = (const int*)d_in[1];
    const int* ecols = (const int*)d_in[2];
    const float* evals = (const float*)d_in[3];
    const float* gat_Ws = (const float*)d_in[4];
    const float* gat_bs = (const float*)d_in[5];
    const float* gat_Wn = (const float*)d_in[6];
    const float* gat_bn = (const float*)d_in[7];
    const float* gat_as = (const float*)d_in[8];
    const float* gat_an = (const float*)d_in[9];
    const float* gcn_W = (const float*)d_in[10];
    const float* gcn_b = (const float*)d_in[11];
    const float* self_W = (const float*)d_in[12];
    const float* self_b = (const float*)d_in[13];
    const float* cls_W = (const float*)d_in[14];
    const float* cls_b = (const float*)d_in[15];
    float* out = (float*)d_out;

    float *buf0, *buf1, *buf2, *atts, *attn, *cc, *stats, *wpack;
    cudaGetSymbolAddress((void**)&buf0, g_buf0);
    cudaGetSymbolAddress((void**)&buf1, g_buf1);
    cudaGetSymbolAddress((void**)&buf2, g_buf2);
    cudaGetSymbolAddress((void**)&atts, g_atts);
    cudaGetSymbolAddress((void**)&attn, g_attn);
    cudaGetSymbolAddress((void**)&cc, g_concat);
    cudaGetSymbolAddress((void**)&stats, g_stats);
    cudaGetSymbolAddress((void**)&wpack, g_wpack);

    dim3 ggrid(cdiv(NNODES, 64), 4);
    const int feat4 = NNODES * DIM / 4;
    const int featBlocks = cdiv(feat4, 256);
    const int normBlocks = cdiv(NNODES * DIM, 256);
    const dim3 eblock(64, 4);
    const int egrid = cdiv(NEDGE, 4);

    // ===== GAT branch (adj 0) =====
    repack_kernel<<<cdiv(2 * HEADS * DIM * DHEAD, 256), 256>>>(gat_Ws, gat_Wn);
    {
        const float* f = f_in;
        for (int l = 0; l < 2; ++l) {
            const float* Wself = wpack + (size_t)l * 2 * DIM * DIM;
            const float* Wnei = Wself + DIM * DIM;
            gemm_kernel<true><<<ggrid, 256>>>(f, Wself, gat_bs + l * 256, buf0);  // f_self
            gemm_kernel<true><<<ggrid, 256>>>(f, Wnei, gat_bn + l * 256, buf2);   // f_neigh
            att_kernel<<<cdiv(NNODES * HEADS, 256), 256>>>(buf0, gat_as + l * 256,
                                                           gat_an + l * 256, atts, attn);
            zero_kernel<<<featBlocks, 256>>>(buf1, feat4);
            gat_edge_kernel<<<egrid, eblock>>>(erows, ecols, evals, atts, attn, buf2, buf1);
            zero_kernel<<<1, 128>>>(stats, 128);
            bn_stats_kernel<false><<<cdiv(NNODES, 256), 256>>>(buf1, stats);
            if (l == 0) {
                bn_norm_kernel<false><<<normBlocks, 256>>>(buf1, stats, buf1, 256);
                f = buf1;
            } else {
                bn_norm_kernel<false><<<normBlocks, 256>>>(buf1, stats, cc + 0, CONCATD);
            }
        }
    }

    // ===== 3 vanilla GCN branches (adjs 1..3) =====
    for (int g = 0; g < 3; ++g) {
        const int* er = erows + (size_t)(g + 1) * NEDGE;
        const int* ec = ecols + (size_t)(g + 1) * NEDGE;
        const float* ev = evals + (size_t)(g + 1) * NEDGE;
        const float* f = f_in;
        for (int l = 0; l < 2; ++l) {
            const float* W = gcn_W + (size_t)(g * 2 + l) * DIM * DIM;
            const float* b = gcn_b + (size_t)(g * 2 + l) * DIM;
            gemm_kernel<false><<<ggrid, 256>>>(f, W, b, buf0);
            zero_kernel<<<featBlocks, 256>>>(buf2, feat4);
            gcn_edge_kernel<<<egrid, eblock>>>(er, ec, ev, buf0, buf2);
            zero_kernel<<<1, 128>>>(stats, 128);
            bn_stats_kernel<true><<<cdiv(NNODES, 256), 256>>>(buf2, stats);
            if (l == 0) {
                bn_norm_kernel<true><<<normBlocks, 256>>>(buf2, stats, buf1, 256);
                f = buf1;
            } else {
                bn_norm_kernel<true><<<normBlocks, 256>>>(buf2, stats, cc + (1 + g) * 256, CONCATD);
            }
        }
    }

    // ===== self perceptron branch =====
    gemm_kernel<true><<<ggrid, 256>>>(f_in, self_W, self_b, buf0);  // relu in epilogue
    zero_kernel<<<1, 128>>>(stats, 128);
    bn_stats_kernel<false><<<cdiv(NNODES, 256), 256>>>(buf0, stats);
    bn_norm_kernel<false><<<normBlocks, 256>>>(buf0, stats, cc + 4 * 256, CONCATD);

    // ===== classifier =====
    cls_kernel<<<cdiv(NNODES, 8), 256>>>(cc, cls_W, cls_b, out);
}

// round 8
// speedup vs baseline: 1.4270x; 1.4270x over previous
#include <cuda_runtime.h>

#define NNODES 50000
#define DIM 256
#define NEDGE 400000
#define HEADS 8
#define DHEAD 32
#define CONCATD 1280
#define NCLS 7
#define EPSBN 1e-9f

static inline int cdiv(int a, int b) { return (a + b - 1) / b; }

// ---------------- scratch (device globals; no allocations allowed) ----------
__device__ float g_buf0[NNODES * DIM];
__device__ float g_buf1[NNODES * DIM];
__device__ float g_buf2[NNODES * DIM];
__device__ float g_atts[NNODES * HEADS];
__device__ float g_attn[NNODES * HEADS];
__device__ float g_concat[NNODES * CONCATD];
__device__ float g_stats[2 * DIM];
__device__ float g_wpack[2 * 2 * DIM * DIM];  // [layer][self/neigh][d][h*32+k]

// ---------------- utility ----------------
__global__ void zero_kernel(float* p, size_t n4) {
    size_t i = (blockIdx.x * (size_t)blockDim.x + threadIdx.x);
    if (i < n4) reinterpret_cast<float4*>(p)[i] = make_float4(0.f, 0.f, 0.f, 0.f);
}

// Repack gat W [2,8,256,32] -> [2][2][256][256] flat (d-major, col = h*32+k)
__global__ void repack_kernel(const float* __restrict__ Ws, const float* __restrict__ Wn) {
    int idx = blockIdx.x * blockDim.x + threadIdx.x;
    if (idx >= 2 * HEADS * DIM * DHEAD) return;
    int l = idx / (HEADS * DIM * DHEAD);
    int rem = idx % (HEADS * DIM * DHEAD);
    int h = rem / (DIM * DHEAD);
    int d = (rem / DHEAD) % DIM;
    int k = rem % DHEAD;
    int dst = l * (2 * DIM * DIM) + d * DIM + h * DHEAD + k;
    g_wpack[dst] = Ws[idx];
    g_wpack[dst + DIM * DIM] = Wn[idx];
}

// ---------------- GEMM: C[M,256] = (relu?)(A[M,256] @ B[256,256] + bias) ----
// BM=128, BN=128, BK=8, 256 threads, 8x8 per thread as 2x2 quads of 4x4.
template <bool RELU>
__global__ __launch_bounds__(256, 2) void gemm128_kernel(const float* __restrict__ A,
                                                         const float* __restrict__ B,
                                                         const float* __restrict__ bias,
                                                         float* __restrict__ C, int M) {
    __shared__ float As[8][132];
    __shared__ float Bs[8][128];
    int tid = threadIdx.x;
    int m0 = blockIdx.x * 128;
    int n0 = blockIdx.y * 128;
    int arow = tid >> 1;        // 0..127
    int acol = (tid & 1) * 4;   // 0 or 4
    int brow = tid >> 5;        // 0..7
    int bcol = (tid & 31) * 4;  // 0..124
    int tx = tid & 15, ty = tid >> 4;
    bool aval = (m0 + arow) < M;
    const float* Aptr = A + (size_t)(m0 + arow) * DIM + acol;
    float acc[2][2][4][4] = {};
    for (int k0 = 0; k0 < DIM; k0 += 8) {
        float4 av = aval ? *reinterpret_cast<const float4*>(Aptr + k0)
                         : make_float4(0.f, 0.f, 0.f, 0.f);
        As[acol + 0][arow] = av.x;
        As[acol + 1][arow] = av.y;
        As[acol + 2][arow] = av.z;
        As[acol + 3][arow] = av.w;
        *reinterpret_cast<float4*>(&Bs[brow][bcol]) =
            *reinterpret_cast<const float4*>(B + (size_t)(k0 + brow) * DIM + n0 + bcol);
        __syncthreads();
#pragma unroll
        for (int k = 0; k < 8; ++k) {
            float a0[4], a1[4], b0[4], b1[4];
            *reinterpret_cast<float4*>(a0) = *reinterpret_cast<float4*>(&As[k][ty * 4]);
            *reinterpret_cast<float4*>(a1) = *reinterpret_cast<float4*>(&As[k][64 + ty * 4]);
            *reinterpret_cast<float4*>(b0) = *reinterpret_cast<float4*>(&Bs[k][tx * 4]);
            *reinterpret_cast<float4*>(b1) = *reinterpret_cast<float4*>(&Bs[k][64 + tx * 4]);
#pragma unroll
            for (int i = 0; i < 4; ++i)
#pragma unroll
                for (int j = 0; j < 4; ++j) {
                    acc[0][0][i][j] += a0[i] * b0[j];
                    acc[0][1][i][j] += a0[i] * b1[j];
                    acc[1][0][i][j] += a1[i] * b0[j];
                    acc[1][1][i][j] += a1[i] * b1[j];
                }
        }
        __syncthreads();
    }
#pragma unroll
    for (int ri = 0; ri < 2; ++ri)
#pragma unroll
        for (int i = 0; i < 4; ++i) {
            int m = m0 + ri * 64 + ty * 4 + i;
            if (m >= M) continue;
#pragma unroll
            for (int ci = 0; ci < 2; ++ci) {
                int n = n0 + ci * 64 + tx * 4;
                float4 bv = *reinterpret_cast<const float4*>(bias + n);
                float4 v;
                v.x = acc[ri][ci][i][0] + bv.x;
                v.y = acc[ri][ci][i][1] + bv.y;
                v.z = acc[ri][ci][i][2] + bv.z;
                v.w = acc[ri][ci][i][3] + bv.w;
                if (RELU) {
                    v.x = fmaxf(v.x, 0.f);
                    v.y = fmaxf(v.y, 0.f);
                    v.z = fmaxf(v.z, 0.f);
                    v.w = fmaxf(v.w, 0.f);
                }
                *reinterpret_cast<float4*>(C + (size_t)m * DIM + n) = v;
            }
        }
}

// ---------------- GAT attention logits (smem-staged, conflict-free) --------
// Block: 256 threads, 32 nodes. warp w handles head w, lane l handles node l.
__global__ __launch_bounds__(256) void att_kernel(const float* __restrict__ fself,
                                                  const float* __restrict__ a_s,
                                                  const float* __restrict__ a_n,
                                                  float* __restrict__ att_s,
                                                  float* __restrict__ att_n) {
    __shared__ float sf[32 * 257];
    __shared__ float sa_s[256], sa_n[256];
    int tid = threadIdx.x;
    int n0 = blockIdx.x * 32;
    int nvalid = min(32, NNODES - n0);
    sa_s[tid] = a_s[tid];
    sa_n[tid] = a_n[tid];
    for (int i = tid; i < nvalid * 256; i += 256) {
        int node = i >> 8, j = i & 255;
        sf[node * 257 + j] = fself[(size_t)(n0 + node) * 256 + j];
    }
    __syncthreads();
    int h = tid >> 5, node = tid & 31;
    if (node < nvalid) {
        const float* f = &sf[node * 257 + h * 32];
        float ss = 0.f, sn = 0.f;
#pragma unroll
        for (int k = 0; k < 32; ++k) {
            float v = f[k];
            ss += v * sa_s[h * 32 + k];
            sn += v * sa_n[h * 32 + k];
        }
        int o = (n0 + node) * 8 + h;
        att_s[o] = ss < 0.f ? 0.2f * ss : ss;
        att_n[o] = sn < 0.f ? 0.2f * sn : sn;
    }
}

// ---------------- edge aggregation (vectorized red.global) ----------------
__device__ __forceinline__ void red_add_v4(float* p, float x, float y, float z, float w) {
    asm volatile("red.global.add.v4.f32 [%0], {%1,%2,%3,%4};" ::"l"(p), "f"(x), "f"(y), "f"(z),
                 "f"(w)
                 : "memory");
}

// blockDim = (64, 4): 64 lanes per edge, 4 edges per block
__global__ void gat_edge_kernel(const int* __restrict__ row, const int* __restrict__ col,
                                const float* __restrict__ vals, const float* __restrict__ att_s,
                                const float* __restrict__ att_n, const float* __restrict__ fneigh,
                                float* __restrict__ out) {
    int e = blockIdx.x * 4 + threadIdx.y;
    if (e >= NEDGE) return;
    int r = row[e], c = col[e];
    int t = threadIdx.x;  // 0..63
    int h = t >> 3;
    float coef = (att_s[r * 8 + h] + att_n[c * 8 + h]) * vals[e];
    float4 fn = *reinterpret_cast<const float4*>(fneigh + (size_t)c * 256 + t * 4);
    red_add_v4(out + (size_t)r * 256 + t * 4, coef * fn.x, coef * fn.y, coef * fn.z, coef * fn.w);
}

__global__ void gcn_edge_kernel(const int* __restrict__ row, const int* __restrict__ col,
                                const float* __restrict__ vals, const float* __restrict__ h,
                                float* __restrict__ out) {
    int e = blockIdx.x * 4 + threadIdx.y;
    if (e >= NEDGE) return;
    int r = row[e], c = col[e];
    float coef = vals[e];
    int t = threadIdx.x;
    float4 fn = *reinterpret_cast<const float4*>(h + (size_t)c * 256 + t * 4);
    red_add_v4(out + (size_t)r * 256 + t * 4, coef * fn.x, coef * fn.y, coef * fn.z, coef * fn.w);
}

// ---------------- BatchNorm (training-mode, biased var) ----------------
template <bool RELU>
__global__ void bn_stats_kernel(const float* __restrict__ x, float* __restrict__ stats) {
    int col = threadIdx.x;  // 256 threads
    int r0 = blockIdx.x * 256;
    int rend = min(r0 + 256, NNODES);
    float s = 0.f, s2 = 0.f;
    for (int r = r0; r < rend; ++r) {
        float v = x[(size_t)r * 256 + col];
        if (RELU) v = fmaxf(v, 0.f);
        s += v;
        s2 += v * v;
    }
    atomicAdd(&stats[col], s);
    atomicAdd(&stats[256 + col], s2);
}

template <bool RELU>
__global__ void bn_norm_kernel(const float* __restrict__ x, const float* __restrict__ stats,
                               float* __restrict__ dst, int dstStride) {
    size_t idx = blockIdx.x * (size_t)blockDim.x + threadIdx.x;
    if (idx >= (size_t)NNODES * 256) return;
    int col = (int)(idx & 255);
    size_t rowi = idx >> 8;
    const float invM = 1.f / NNODES;
    float mean = stats[col] * invM;
    float var = stats[256 + col] * invM - mean * mean;
    float istd = rsqrtf(var + EPSBN);
    float v = x[idx];
    if (RELU) v = fmaxf(v, 0.f);
    dst[rowi * dstStride + col] = (v - mean) * istd;
}

// ---------------- classifier: [N,1280] @ [1280,7] + b ----------------
__global__ void cls_kernel(const float* __restrict__ feat, const float* __restrict__ W,
                           const float* __restrict__ b, float* __restrict__ out) {
    __shared__ float sW[CONCATD * NCLS];
    for (int i = threadIdx.x; i < CONCATD * NCLS; i += blockDim.x) sW[i] = W[i];
    __syncthreads();
    int warp = threadIdx.x >> 5, lane = threadIdx.x & 31;
    int n = blockIdx.x * (blockDim.x >> 5) + warp;
    if (n >= NNODES) return;
    float acc[NCLS] = {};
    const float* f = feat + (size_t)n * CONCATD;
    for (int j = lane; j < CONCATD; j += 32) {
        float v = f[j];
#pragma unroll
        for (int c = 0; c < NCLS; ++c) acc[c] += v * sW[j * NCLS + c];
    }
#pragma unroll
    for (int c = 0; c < NCLS; ++c)
        for (int off = 16; off; off >>= 1) acc[c] += __shfl_down_sync(0xffffffffu, acc[c], off);
    if (lane == 0) {
#pragma unroll
        for (int c = 0; c < NCLS; ++c) out[(size_t)n * NCLS + c] = acc[c] + b[c];
    }
}

// ---------------- host orchestration ----------------
extern "C" void kernel_launch(void* const* d_in, const int* in_sizes, int n_in,
                              void* d_out, int out_size) {
    const float* f_in = (const float*)d_in[0];
    const int* erows = (const int*)d_in[1];
    const int* ecols = (const int*)d_in[2];
    const float* evals = (const float*)d_in[3];
    const float* gat_Ws = (const float*)d_in[4];
    const float* gat_bs = (const float*)d_in[5];
    const float* gat_Wn = (const float*)d_in[6];
    const float* gat_bn = (const float*)d_in[7];
    const float* gat_as = (const float*)d_in[8];
    const float* gat_an = (const float*)d_in[9];
    const float* gcn_W = (const float*)d_in[10];
    const float* gcn_b = (const float*)d_in[11];
    const float* self_W = (const float*)d_in[12];
    const float* self_b = (const float*)d_in[13];
    const float* cls_W = (const float*)d_in[14];
    const float* cls_b = (const float*)d_in[15];
    float* out = (float*)d_out;

    float *buf0, *buf1, *buf2, *atts, *attn, *cc, *stats, *wpack;
    cudaGetSymbolAddress((void**)&buf0, g_buf0);
    cudaGetSymbolAddress((void**)&buf1, g_buf1);
    cudaGetSymbolAddress((void**)&buf2, g_buf2);
    cudaGetSymbolAddress((void**)&atts, g_atts);
    cudaGetSymbolAddress((void**)&attn, g_attn);
    cudaGetSymbolAddress((void**)&cc, g_concat);
    cudaGetSymbolAddress((void**)&stats, g_stats);
    cudaGetSymbolAddress((void**)&wpack, g_wpack);

    dim3 ggrid(cdiv(NNODES, 128), 2);
    const int feat4 = NNODES * DIM / 4;
    const int featBlocks = cdiv(feat4, 256);
    const int normBlocks = cdiv(NNODES * DIM, 256);
    const dim3 eblock(64, 4);
    const int egrid = cdiv(NEDGE, 4);

    // ===== GAT branch (adj 0) =====
    repack_kernel<<<cdiv(2 * HEADS * DIM * DHEAD, 256), 256>>>(gat_Ws, gat_Wn);
    {
        const float* f = f_in;
        for (int l = 0; l < 2; ++l) {
            const float* Wself = wpack + (size_t)l * 2 * DIM * DIM;
            const float* Wnei = Wself + DIM * DIM;
            gemm128_kernel<true><<<ggrid, 256>>>(f, Wself, gat_bs + l * 256, buf0, NNODES);
            gemm128_kernel<true><<<ggrid, 256>>>(f, Wnei, gat_bn + l * 256, buf2, NNODES);
            att_kernel<<<cdiv(NNODES, 32), 256>>>(buf0, gat_as + l * 256, gat_an + l * 256, atts,
                                                  attn);
            zero_kernel<<<featBlocks, 256>>>(buf1, feat4);
            gat_edge_kernel<<<egrid, eblock>>>(erows, ecols, evals, atts, attn, buf2, buf1);
            zero_kernel<<<1, 128>>>(stats, 128);
            bn_stats_kernel<false><<<cdiv(NNODES, 256), 256>>>(buf1, stats);
            if (l == 0) {
                bn_norm_kernel<false><<<normBlocks, 256>>>(buf1, stats, buf1, 256);
                f = buf1;
            } else {
                bn_norm_kernel<false><<<normBlocks, 256>>>(buf1, stats, cc + 0, CONCATD);
            }
        }
    }

    // ===== 3 vanilla GCN branches (adjs 1..3) =====
    for (int g = 0; g < 3; ++g) {
        const int* er = erows + (size_t)(g + 1) * NEDGE;
        const int* ec = ecols + (size_t)(g + 1) * NEDGE;
        const float* ev = evals + (size_t)(g + 1) * NEDGE;
        const float* f = f_in;
        for (int l = 0; l < 2; ++l) {
            const float* W = gcn_W + (size_t)(g * 2 + l) * DIM * DIM;
            const float* b = gcn_b + (size_t)(g * 2 + l) * DIM;
            gemm128_kernel<false><<<ggrid, 256>>>(f, W, b, buf0, NNODES);
            zero_kernel<<<featBlocks, 256>>>(buf2, feat4);
            gcn_edge_kernel<<<egrid, eblock>>>(er, ec, ev, buf0, buf2);
            zero_kernel<<<1, 128>>>(stats, 128);
            bn_stats_kernel<true><<<cdiv(NNODES, 256), 256>>>(buf2, stats);
            if (l == 0) {
                bn_norm_kernel<true><<<normBlocks, 256>>>(buf2, stats, buf1, 256);
                f = buf1;
            } else {
                bn_norm_kernel<true><<<normBlocks, 256>>>(buf2, stats, cc + (1 + g) * 256, CONCATD);
            }
        }
    }

    // ===== self perceptron branch =====
    gemm128_kernel<true><<<ggrid, 256>>>(f_in, self_W, self_b, buf0, NNODES);
    zero_kernel<<<1, 128>>>(stats, 128);
    bn_stats_kernel<false><<<cdiv(NNODES, 256), 256>>>(buf0, stats);
    bn_norm_kernel<false><<<normBlocks, 256>>>(buf0, stats, cc + 4 * 256, CONCATD);

    // ===== classifier =====
    cls_kernel<<<cdiv(NNODES, 8), 256>>>(cc, cls_W, cls_b, out);
}

// round 12
// speedup vs baseline: 2.1253x; 1.4894x over previous
#include <cuda_runtime.h>
#include <cuda_bf16.h>
#include <cstdint>

#define NNODES 50000
#define DIM 256
#define NEDGE 400000
#define HEADS 8
#define DHEAD 32
#define CONCATD 1280
#define NCLS 7
#define EPSBN 1e-9f

static inline int cdiv(int a, int b) { return (a + b - 1) / b; }

// ---------------- scratch (device globals; no allocations allowed) ----------
__device__ float g_buf0[NNODES * DIM];
__device__ float g_buf1[NNODES * DIM];
__device__ float g_buf2[NNODES * DIM];
__device__ float g_atts[NNODES * HEADS];
__device__ float g_attn[NNODES * HEADS];
__device__ float g_concat[NNODES * CONCATD];
__device__ float g_stats[2 * DIM];
__device__ float g_wpack[2 * 2 * DIM * DIM];  // GAT repacked fp32 [l][s/n][d][h*32+k]
__device__ __nv_bfloat16 g_fin_hi[NNODES * DIM];
__device__ __nv_bfloat16 g_fin_lo[NNODES * DIM];
__device__ __nv_bfloat16 g_act_hi[NNODES * DIM];
__device__ __nv_bfloat16 g_act_lo[NNODES * DIM];
__device__ __nv_bfloat16 g_wt_hi[11 * DIM * DIM];  // [widx][n][k] bf16 (transposed)
__device__ __nv_bfloat16 g_wt_lo[11 * DIM * DIM];

// ---------------- utility ----------------
__global__ void zero_kernel(float* p, size_t n4) {
    size_t i = (blockIdx.x * (size_t)blockDim.x + threadIdx.x);
    if (i < n4) reinterpret_cast<float4*>(p)[i] = make_float4(0.f, 0.f, 0.f, 0.f);
}

// Repack gat W [2,8,256,32] -> [2][2][256][256] flat (d-major, col = h*32+k)
__global__ void repack_kernel(const float* __restrict__ Ws, const float* __restrict__ Wn) {
    int idx = blockIdx.x * blockDim.x + threadIdx.x;
    if (idx >= 2 * HEADS * DIM * DHEAD) return;
    int l = idx / (HEADS * DIM * DHEAD);
    int rem = idx % (HEADS * DIM * DHEAD);
    int h = rem / (DIM * DHEAD);
    int d = (rem / DHEAD) % DIM;
    int k = rem % DHEAD;
    int dst = l * (2 * DIM * DIM) + d * DIM + h * DHEAD + k;
    g_wpack[dst] = Ws[idx];
    g_wpack[dst + DIM * DIM] = Wn[idx];
}

// Transpose + split one [K=256,N=256] fp32 weight -> [N][K] bf16 hi/lo
__global__ void wsplit_kernel(const float* __restrict__ src, __nv_bfloat16* __restrict__ dh,
                              __nv_bfloat16* __restrict__ dl) {
    int idx = blockIdx.x * blockDim.x + threadIdx.x;
    if (idx >= DIM * DIM) return;
    int n = idx >> 8, k = idx & 255;
    float v = src[k * DIM + n];
    __nv_bfloat16 hi = __float2bfloat16(v);
    dh[idx] = hi;
    dl[idx] = __float2bfloat16(v - __bfloat162float(hi));
}

// Split fp32 features -> bf16 hi/lo
__global__ void fsplit_kernel(const float* __restrict__ src, __nv_bfloat16* __restrict__ dh,
                              __nv_bfloat16* __restrict__ dl) {
    size_t idx = blockIdx.x * (size_t)blockDim.x + threadIdx.x;
    if (idx >= (size_t)NNODES * DIM) return;
    float v = src[idx];
    __nv_bfloat16 hi = __float2bfloat16(v);
    dh[idx] = hi;
    dl[idx] = __float2bfloat16(v - __bfloat162float(hi));
}

// ---------------- mma.sync bf16-split GEMM ----------------------------------
// C[M,256](n-slice) = (relu?)(A @ Wt^T + bias), A ~ Ah+Al, W ~ Wh+Wl
// C ≈ Ah·Bh + Ah·Bl + Al·Bh  (3-term, rel err ~2^-16)
// CTA: 128x128 tile, 8 warps (2m x 4n), warp tile 64x32, BK=64.
#define BK 64
#define ASTR 72  // BK + 8 pad (bf16 elems); row byte stride 144 -> conflict-free frags

__device__ __forceinline__ void mma16816(float* c, const uint32_t* a, const uint32_t* b) {
    asm volatile(
        "mma.sync.aligned.m16n8k16.row.col.f32.bf16.bf16.f32 "
        "{%0,%1,%2,%3}, {%4,%5,%6,%7}, {%8,%9}, {%0,%1,%2,%3};"
        : "+f"(c[0]), "+f"(c[1]), "+f"(c[2]), "+f"(c[3])
        : "r"(a[0]), "r"(a[1]), "r"(a[2]), "r"(a[3]), "r"(b[0]), "r"(b[1]));
}

template <bool RELU>
__global__ __launch_bounds__(256, 2) void gemm_mma_kernel(
    const __nv_bfloat16* __restrict__ Ah, const __nv_bfloat16* __restrict__ Al,
    const __nv_bfloat16* __restrict__ Bh, const __nv_bfloat16* __restrict__ Bl,
    const float* __restrict__ bias, float* __restrict__ C, int M) {
    extern __shared__ __nv_bfloat16 sm[];
    __nv_bfloat16* sAh = sm;                 // 128*72
    __nv_bfloat16* sAl = sm + 128 * ASTR;    // 128*72
    __nv_bfloat16* sBh = sm + 2 * 128 * ASTR;
    __nv_bfloat16* sBl = sm + 3 * 128 * ASTR;

    int tid = threadIdx.x;
    int wid = tid >> 5, lane = tid & 31;
    int m0 = blockIdx.x * 128;
    int n0 = blockIdx.y * 128;
    int wm = (wid >> 2) * 64;   // warp m origin in tile
    int wn = (wid & 3) * 32;    // warp n origin in tile
    int lg = lane >> 2;         // group id 0..7
    int lt = lane & 3;          // thread-in-group

    float acc[4][4][4] = {};  // [mt][nt][reg]

    for (int k0 = 0; k0 < DIM; k0 += BK) {
        // stage: 128 rows x 64 bf16 per array; 8 uint4/row -> 1024 uint4, 4/thread
        for (int i = tid; i < 1024; i += 256) {
            int r = i >> 3;
            int c8 = (i & 7) * 8;  // bf16 col
            int soff = r * ASTR + c8;
            int m = m0 + r;
            uint4 vh = make_uint4(0, 0, 0, 0), vl = make_uint4(0, 0, 0, 0);
            if (m < M) {
                vh = *reinterpret_cast<const uint4*>(Ah + (size_t)m * DIM + k0 + c8);
                vl = *reinterpret_cast<const uint4*>(Al + (size_t)m * DIM + k0 + c8);
            }
            *reinterpret_cast<uint4*>(sAh + soff) = vh;
            *reinterpret_cast<uint4*>(sAl + soff) = vl;
            // B rows are n-indices (n0..n0+127 < 256 always)
            *reinterpret_cast<uint4*>(sBh + soff) =
                *reinterpret_cast<const uint4*>(Bh + (size_t)(n0 + r) * DIM + k0 + c8);
            *reinterpret_cast<uint4*>(sBl + soff) =
                *reinterpret_cast<const uint4*>(Bl + (size_t)(n0 + r) * DIM + k0 + c8);
        }
        __syncthreads();

#pragma unroll
        for (int kk = 0; kk < BK; kk += 16) {
            // B fragments for all 4 n-tiles (hi & lo)
            uint32_t bh[4][2], bl[4][2];
#pragma unroll
            for (int nt = 0; nt < 4; ++nt) {
                int n = wn + nt * 8 + lg;
                int k = kk + lt * 2;
                bh[nt][0] = *reinterpret_cast<uint32_t*>(sBh + n * ASTR + k);
                bh[nt][1] = *reinterpret_cast<uint32_t*>(sBh + n * ASTR + k + 8);
                bl[nt][0] = *reinterpret_cast<uint32_t*>(sBl + n * ASTR + k);
                bl[nt][1] = *reinterpret_cast<uint32_t*>(sBl + n * ASTR + k + 8);
            }
#pragma unroll
            for (int mt = 0; mt < 4; ++mt) {
                int r = wm + mt * 16 + lg;
                int k = kk + lt * 2;
                uint32_t ah[4], al[4];
                ah[0] = *reinterpret_cast<uint32_t*>(sAh + r * ASTR + k);
                ah[1] = *reinterpret_cast<uint32_t*>(sAh + (r + 8) * ASTR + k);
                ah[2] = *reinterpret_cast<uint32_t*>(sAh + r * ASTR + k + 8);
                ah[3] = *reinterpret_cast<uint32_t*>(sAh + (r + 8) * ASTR + k + 8);
                al[0] = *reinterpret_cast<uint32_t*>(sAl + r * ASTR + k);
                al[1] = *reinterpret_cast<uint32_t*>(sAl + (r + 8) * ASTR + k);
                al[2] = *reinterpret_cast<uint32_t*>(sAl + r * ASTR + k + 8);
                al[3] = *reinterpret_cast<uint32_t*>(sAl + (r + 8) * ASTR + k + 8);
#pragma unroll
                for (int nt = 0; nt < 4; ++nt) {
                    mma16816(acc[mt][nt], ah, bh[nt]);  // hi*hi
                    mma16816(acc[mt][nt], ah, bl[nt]);  // hi*lo
                    mma16816(acc[mt][nt], al, bh[nt]);  // lo*hi
                }
            }
        }
        __syncthreads();
    }

    // epilogue: c0,c1 -> (row, col..col+1); c2,c3 -> (row+8, ...)
#pragma unroll
    for (int mt = 0; mt < 4; ++mt) {
        int r = m0 + wm + mt * 16 + lg;
#pragma unroll
        for (int nt = 0; nt < 4; ++nt) {
            int col = n0 + wn + nt * 8 + lt * 2;
            float2 bv = *reinterpret_cast<const float2*>(bias + col);
            if (r < M) {
                float2 v;
                v.x = acc[mt][nt][0] + bv.x;
                v.y = acc[mt][nt][1] + bv.y;
                if (RELU) {
                    v.x = fmaxf(v.x, 0.f);
                    v.y = fmaxf(v.y, 0.f);
                }
                *reinterpret_cast<float2*>(C + (size_t)r * DIM + col) = v;
            }
            if (r + 8 < M) {
                float2 v;
                v.x = acc[mt][nt][2] + bv.x;
                v.y = acc[mt][nt][3] + bv.y;
                if (RELU) {
                    v.x = fmaxf(v.x, 0.f);
                    v.y = fmaxf(v.y, 0.f);
                }
                *reinterpret_cast<float2*>(C + (size_t)(r + 8) * DIM + col) = v;
            }
        }
    }
}

#define SMEM_MMA (4 * 128 * ASTR * 2)  // 73728 bytes

// ---------------- GAT attention logits (smem-staged, conflict-free) --------
__global__ __launch_bounds__(256) void att_kernel(const float* __restrict__ fself,
                                                  const float* __restrict__ a_s,
                                                  const float* __restrict__ a_n,
                                                  float* __restrict__ att_s,
                                                  float* __restrict__ att_n) {
    __shared__ float sf[32 * 257];
    __shared__ float sa_s[256], sa_n[256];
    int tid = threadIdx.x;
    int n0 = blockIdx.x * 32;
    int nvalid = min(32, NNODES - n0);
    sa_s[tid] = a_s[tid];
    sa_n[tid] = a_n[tid];
    for (int i = tid; i < nvalid * 256; i += 256) {
        int node = i >> 8, j = i & 255;
        sf[node * 257 + j] = fself[(size_t)(n0 + node) * 256 + j];
    }
    __syncthreads();
    int h = tid >> 5, node = tid & 31;
    if (node < nvalid) {
        const float* f = &sf[node * 257 + h * 32];
        float ss = 0.f, sn = 0.f;
#pragma unroll
        for (int k = 0; k < 32; ++k) {
            float v = f[k];
            ss += v * sa_s[h * 32 + k];
            sn += v * sa_n[h * 32 + k];
        }
        int o = (n0 + node) * 8 + h;
        att_s[o] = ss < 0.f ? 0.2f * ss : ss;
        att_n[o] = sn < 0.f ? 0.2f * sn : sn;
    }
}

// ---------------- edge aggregation (vectorized red.global) ----------------
__device__ __forceinline__ void red_add_v4(float* p, float x, float y, float z, float w) {
    asm volatile("red.global.add.v4.f32 [%0], {%1,%2,%3,%4};" ::"l"(p), "f"(x), "f"(y), "f"(z),
                 "f"(w)
                 : "memory");
}

__global__ void gat_edge_kernel(const int* __restrict__ row, const int* __restrict__ col,
                                const float* __restrict__ vals, const float* __restrict__ att_s,
                                const float* __restrict__ att_n, const float* __restrict__ fneigh,
                                float* __restrict__ out) {
    int e = blockIdx.x * 4 + threadIdx.y;
    if (e >= NEDGE) return;
    int r = row[e], c = col[e];
    int t = threadIdx.x;  // 0..63
    int h = t >> 3;
    float coef = (att_s[r * 8 + h] + att_n[c * 8 + h]) * vals[e];
    float4 fn = *reinterpret_cast<const float4*>(fneigh + (size_t)c * 256 + t * 4);
    red_add_v4(out + (size_t)r * 256 + t * 4, coef * fn.x, coef * fn.y, coef * fn.z, coef * fn.w);
}

__global__ void gcn_edge_kernel(const int* __restrict__ row, const int* __restrict__ col,
                                const float* __restrict__ vals, const float* __restrict__ h,
                                float* __restrict__ out) {
    int e = blockIdx.x * 4 + threadIdx.y;
    if (e >= NEDGE) return;
    int r = row[e], c = col[e];
    float coef = vals[e];
    int t = threadIdx.x;
    float4 fn = *reinterpret_cast<const float4*>(h + (size_t)c * 256 + t * 4);
    red_add_v4(out + (size_t)r * 256 + t * 4, coef * fn.x, coef * fn.y, coef * fn.z, coef * fn.w);
}

// ---------------- BatchNorm (training-mode, biased var) ----------------
template <bool RELU>
__global__ void bn_stats_kernel(const float* __restrict__ x, float* __restrict__ stats) {
    int col = threadIdx.x;  // 256 threads
    int r0 = blockIdx.x * 256;
    int rend = min(r0 + 256, NNODES);
    float s = 0.f, s2 = 0.f;
    for (int r = r0; r < rend; ++r) {
        float v = x[(size_t)r * 256 + col];
        if (RELU) v = fmaxf(v, 0.f);
        s += v;
        s2 += v * v;
    }
    atomicAdd(&stats[col], s);
    atomicAdd(&stats[256 + col], s2);
}

template <bool RELU>
__global__ void bn_norm_kernel(const float* __restrict__ x, const float* __restrict__ stats,
                               float* __restrict__ dst, int dstStride) {
    size_t idx = blockIdx.x * (size_t)blockDim.x + threadIdx.x;
    if (idx >= (size_t)NNODES * 256) return;
    int col = (int)(idx & 255);
    size_t rowi = idx >> 8;
    const float invM = 1.f / NNODES;
    float mean = stats[col] * invM;
    float var = stats[256 + col] * invM - mean * mean;
    float istd = rsqrtf(var + EPSBN);
    float v = x[idx];
    if (RELU) v = fmaxf(v, 0.f);
    dst[rowi * dstStride + col] = (v - mean) * istd;
}

// BN normalize fused with bf16 hi/lo split (for layer-0 outputs feeding GEMMs)
template <bool RELU>
__global__ void bn_norm_bf16_kernel(const float* __restrict__ x, const float* __restrict__ stats,
                                    __nv_bfloat16* __restrict__ dh,
                                    __nv_bfloat16* __restrict__ dl) {
    size_t idx = blockIdx.x * (size_t)blockDim.x + threadIdx.x;
    if (idx >= (size_t)NNODES * 256) return;
    int col = (int)(idx & 255);
    const float invM = 1.f / NNODES;
    float mean = stats[col] * invM;
    float var = stats[256 + col] * invM - mean * mean;
    float istd = rsqrtf(var + EPSBN);
    float v = x[idx];
    if (RELU) v = fmaxf(v, 0.f);
    float nv = (v - mean) * istd;
    __nv_bfloat16 hi = __float2bfloat16(nv);
    dh[idx] = hi;
    dl[idx] = __float2bfloat16(nv - __bfloat162float(hi));
}

// ---------------- classifier: [N,1280] @ [1280,7] + b ----------------
__global__ void cls_kernel(const float* __restrict__ feat, const float* __restrict__ W,
                           const float* __restrict__ b, float* __restrict__ out) {
    __shared__ float sW[CONCATD * NCLS];
    for (int i = threadIdx.x; i < CONCATD * NCLS; i += blockDim.x) sW[i] = W[i];
    __syncthreads();
    int warp = threadIdx.x >> 5, lane = threadIdx.x & 31;
    int n = blockIdx.x * (blockDim.x >> 5) + warp;
    if (n >= NNODES) return;
    float acc[NCLS] = {};
    const float* f = feat + (size_t)n * CONCATD;
    for (int j = lane; j < CONCATD; j += 32) {
        float v = f[j];
#pragma unroll
        for (int c = 0; c < NCLS; ++c) acc[c] += v * sW[j * NCLS + c];
    }
#pragma unroll
    for (int c = 0; c < NCLS; ++c)
        for (int off = 16; off; off >>= 1) acc[c] += __shfl_down_sync(0xffffffffu, acc[c], off);
    if (lane == 0) {
#pragma unroll
        for (int c = 0; c < NCLS; ++c) out[(size_t)n * NCLS + c] = acc[c] + b[c];
    }
}

// ---------------- host orchestration ----------------
extern "C" void kernel_launch(void* const* d_in, const int* in_sizes, int n_in,
                              void* d_out, int out_size) {
    const float* f_in = (const float*)d_in[0];
    const int* erows = (const int*)d_in[1];
    const int* ecols = (const int*)d_in[2];
    const float* evals = (const float*)d_in[3];
    const float* gat_Ws = (const float*)d_in[4];
    const float* gat_bs = (const float*)d_in[5];
    const float* gat_Wn = (const float*)d_in[6];
    const float* gat_bn = (const float*)d_in[7];
    const float* gat_as = (const float*)d_in[8];
    const float* gat_an = (const float*)d_in[9];
    const float* gcn_W = (const float*)d_in[10];
    const float* gcn_b = (const float*)d_in[11];
    const float* self_W = (const float*)d_in[12];
    const float* self_b = (const float*)d_in[13];
    const float* cls_W = (const float*)d_in[14];
    const float* cls_b = (const float*)d_in[15];
    float* out = (float*)d_out;

    float *buf0, *buf1, *buf2, *atts, *attn, *cc, *stats, *wpack;
    __nv_bfloat16 *finh, *finl, *acth, *actl, *wth, *wtl;
    cudaGetSymbolAddress((void**)&buf0, g_buf0);
    cudaGetSymbolAddress((void**)&buf1, g_buf1);
    cudaGetSymbolAddress((void**)&buf2, g_buf2);
    cudaGetSymbolAddress((void**)&atts, g_atts);
    cudaGetSymbolAddress((void**)&attn, g_attn);
    cudaGetSymbolAddress((void**)&cc, g_concat);
    cudaGetSymbolAddress((void**)&stats, g_stats);
    cudaGetSymbolAddress((void**)&wpack, g_wpack);
    cudaGetSymbolAddress((void**)&finh, g_fin_hi);
    cudaGetSymbolAddress((void**)&finl, g_fin_lo);
    cudaGetSymbolAddress((void**)&acth, g_act_hi);
    cudaGetSymbolAddress((void**)&actl, g_act_lo);
    cudaGetSymbolAddress((void**)&wth, g_wt_hi);
    cudaGetSymbolAddress((void**)&wtl, g_wt_lo);

    cudaFuncSetAttribute(gemm_mma_kernel<true>, cudaFuncAttributeMaxDynamicSharedMemorySize,
                         SMEM_MMA);
    cudaFuncSetAttribute(gemm_mma_kernel<false>, cudaFuncAttributeMaxDynamicSharedMemorySize,
                         SMEM_MMA);

    const dim3 mgrid(cdiv(NNODES, 128), 2);
    const int feat4 = NNODES * DIM / 4;
    const int featBlocks = cdiv(feat4, 256);
    const int normBlocks = cdiv(NNODES * DIM, 256);
    const dim3 eblock(64, 4);
    const int egrid = cdiv(NEDGE, 4);
    const int wblocks = cdiv(DIM * DIM, 256);
    const size_t WSZ = (size_t)DIM * DIM;

    // ===== weight preparation =====
    repack_kernel<<<cdiv(2 * HEADS * DIM * DHEAD, 256), 256>>>(gat_Ws, gat_Wn);
    for (int i = 0; i < 4; ++i)  // GAT: widx 0..3 = (l0,s),(l0,n),(l1,s),(l1,n)
        wsplit_kernel<<<wblocks, 256>>>(wpack + i * WSZ, wth + i * WSZ, wtl + i * WSZ);
    for (int i = 0; i < 6; ++i)  // GCN: widx 4..9
        wsplit_kernel<<<wblocks, 256>>>(gcn_W + i * WSZ, wth + (4 + i) * WSZ, wtl + (4 + i) * WSZ);
    wsplit_kernel<<<wblocks, 256>>>(self_W, wth + 10 * WSZ, wtl + 10 * WSZ);  // widx 10
    fsplit_kernel<<<normBlocks, 256>>>(f_in, finh, finl);

    // ===== GAT branch (adj 0) =====
    {
        const __nv_bfloat16 *fh = finh, *fl = finl;
        for (int l = 0; l < 2; ++l) {
            const __nv_bfloat16* Wsh = wth + (size_t)(l * 2) * WSZ;
            const __nv_bfloat16* Wsl = wtl + (size_t)(l * 2) * WSZ;
            const __nv_bfloat16* Wnh = wth + (size_t)(l * 2 + 1) * WSZ;
            const __nv_bfloat16* Wnl = wtl + (size_t)(l * 2 + 1) * WSZ;
            gemm_mma_kernel<true><<<mgrid, 256, SMEM_MMA>>>(fh, fl, Wsh, Wsl, gat_bs + l * 256,
                                                            buf0, NNODES);
            gemm_mma_kernel<true><<<mgrid, 256, SMEM_MMA>>>(fh, fl, Wnh, Wnl, gat_bn + l * 256,
                                                            buf2, NNODES);
            att_kernel<<<cdiv(NNODES, 32), 256>>>(buf0, gat_as + l * 256, gat_an + l * 256, atts,
                                                  attn);
            zero_kernel<<<featBlocks, 256>>>(buf1, feat4);
            gat_edge_kernel<<<egrid, eblock>>>(erows, ecols, evals, atts, attn, buf2, buf1);
            zero_kernel<<<1, 128>>>(stats, 128);
            bn_stats_kernel<false><<<cdiv(NNODES, 256), 256>>>(buf1, stats);
            if (l == 0) {
                bn_norm_bf16_kernel<false><<<normBlocks, 256>>>(buf1, stats, acth, actl);
                fh = acth;
                fl = actl;
            } else {
                bn_norm_kernel<false><<<normBlocks, 256>>>(buf1, stats, cc + 0, CONCATD);
            }
        }
    }

    // ===== 3 vanilla GCN branches (adjs 1..3) =====
    for (int g = 0; g < 3; ++g) {
        const int* er = erows + (size_t)(g + 1) * NEDGE;
        const int* ec = ecols + (size_t)(g + 1) * NEDGE;
        const float* ev = evals + (size_t)(g + 1) * NEDGE;
        const __nv_bfloat16 *fh = finh, *fl = finl;
        for (int l = 0; l < 2; ++l) {
            int widx = 4 + g * 2 + l;
            const float* b = gcn_b + (size_t)(g * 2 + l) * DIM;
            gemm_mma_kernel<false><<<mgrid, 256, SMEM_MMA>>>(
                fh, fl, wth + (size_t)widx * WSZ, wtl + (size_t)widx * WSZ, b, buf0, NNODES);
            zero_kernel<<<featBlocks, 256>>>(buf2, feat4);
            gcn_edge_kernel<<<egrid, eblock>>>(er, ec, ev, buf0, buf2);
            zero_kernel<<<1, 128>>>(stats, 128);
            bn_stats_kernel<true><<<cdiv(NNODES, 256), 256>>>(buf2, stats);
            if (l == 0) {
                bn_norm_bf16_kernel<true><<<normBlocks, 256>>>(buf2, stats, acth, actl);
                fh = acth;
                fl = actl;
            } else {
                bn_norm_kernel<true><<<normBlocks, 256>>>(buf2, stats, cc + (1 + g) * 256, CONCATD);
            }
        }
    }

    // ===== self perceptron branch =====
    gemm_mma_kernel<true><<<mgrid, 256, SMEM_MMA>>>(finh, finl, wth + 10 * WSZ, wtl + 10 * WSZ,
                                                    self_b, buf0, NNODES);
    zero_kernel<<<1, 128>>>(stats, 128);
    bn_stats_kernel<false><<<cdiv(NNODES, 256), 256>>>(buf0, stats);
    bn_norm_kernel<false><<<normBlocks, 256>>>(buf0, stats, cc + 4 * 256, CONCATD);

    // ===== classifier =====
    cls_kernel<<<cdiv(NNODES, 8), 256>>>(cc, cls_W, cls_b, out);
}